// round 11
// baseline (speedup 1.0000x reference)
#include <cuda_runtime.h>
#include <cstddef>
#include <cstdint>

#define T_   512
#define B_   64
#define E_   300
#define H_   512
#define L_   5
#define G3H_ 1536
#define NBLK 256      // recurrence CTAs: 64 ug x 4 bg, 2 CTAs/SM
#define NTHR 256
#define GRPSZ 64      // CTAs per batch-group barrier

typedef unsigned long long ull;

// ---------------- scratch (no allocations allowed) ----------------
__device__ float g_xp0[(size_t)T_ * B_ * G3H_];   // 201 MB
__device__ float g_xp1[(size_t)T_ * B_ * G3H_];   // 201 MB
__device__ float g_h1 [(size_t)T_ * B_ * H_];     // 67 MB  (layer0 history, [t*B+b][H])
__device__ float g_hT [2 * H_ * B_];              // h double buffer, [buf][bg4][k512][b16]
__device__ float g_pooledp[4 * T_ * H_];          // per-bg partial sums
__device__ unsigned int g_arrive4[4 * 32];        // one counter per bg, 128B apart

__global__ void init_kernel() {
    if (threadIdx.x < 4 * 32) g_arrive4[threadIdx.x] = 0u;
}

// ---------------- f32x2 helpers (FFMA2 only reachable via PTX) ----------------
__device__ __forceinline__ ull ffma2(ull a, ull b, ull c) {
    ull d;
    asm("fma.rn.f32x2 %0, %1, %2, %3;" : "=l"(d) : "l"(a), "l"(b), "l"(c));
    return d;
}
__device__ __forceinline__ ull pack2(float lo, float hi) {
    ull d;
    asm("mov.b64 %0, {%1, %2};" : "=l"(d) : "f"(lo), "f"(hi));
    return d;
}
__device__ __forceinline__ float2 unpack2(ull v) {
    float2 r;
    asm("mov.b64 {%0, %1}, %2;" : "=f"(r.x), "=f"(r.y) : "l"(v));
    return r;
}
__device__ __forceinline__ uint32_t smem_u32(const void* p) {
    uint32_t a;
    asm("{ .reg .u64 t; cvta.to.shared.u64 t, %1; cvt.u32.u64 %0, t; }" : "=r"(a) : "l"(p));
    return a;
}
__device__ __forceinline__ void cp_async16(uint32_t dst, const void* src) {
    asm volatile("cp.async.cg.shared.global [%0], [%1], 16;" :: "r"(dst), "l"(src));
}

// ---------------- per-group barrier (64 co-resident CTAs sharing one bg) ----------------
__device__ __forceinline__ void group_barrier(unsigned int* epoch, unsigned int* cnt) {
    __syncthreads();
    if (threadIdx.x == 0) {
        __threadfence();
        unsigned int target = (*epoch + 1u) * GRPSZ;
        atomicAdd(cnt, 1u);
        while (*((volatile unsigned int*)cnt) < target) { }
        __threadfence();
    }
    __syncthreads();
    ++(*epoch);
}

// ---------------- fp32 GEMM: C[M,N] = A[M,K] @ W[N,K]^T + bias (R7, unchanged) ----------------
__global__ void __launch_bounds__(256, 2) gemm_kernel(
    const float* __restrict__ A, const int* __restrict__ gather,
    const float* __restrict__ W, const float* __restrict__ bias,
    float* __restrict__ C, int M, int N, int K)
{
    __shared__ __align__(16) float As[32][130];
    __shared__ __align__(16) float Ws[32][68];

    const int tid = threadIdx.x;
    const int tx = tid & 15;
    const int ty = tid >> 4;
    const int m0 = blockIdx.y * 128;
    const int n0 = blockIdx.x * 64;

    const int sq = tid & 7;
    const int sr = tid >> 3;

    const float* arow[4];
    #pragma unroll
    for (int r = 0; r < 4; ++r) {
        int am = m0 + sr + 32 * r;
        if (gather) am = gather[am];
        arow[r] = A + (size_t)am * K;
    }
    const float* wrow[2];
    #pragma unroll
    for (int r = 0; r < 2; ++r)
        wrow[r] = W + (size_t)(n0 + sr + 32 * r) * K;

    ull acc[4][4];
    #pragma unroll
    for (int mp = 0; mp < 4; ++mp)
        #pragma unroll
        for (int n = 0; n < 4; ++n) acc[mp][n] = 0ull;

    const int Kiter = (K + 31) >> 5;

    float4 pa[4], pw[2];
    {
        int k = sq * 4;
        #pragma unroll
        for (int r = 0; r < 4; ++r) {
            if (k + 3 < K) pa[r] = *(const float4*)(arow[r] + k);
            else {
                float4 z = {0.f,0.f,0.f,0.f};
                #pragma unroll
                for (int j = 0; j < 4; ++j) if (k + j < K) ((float*)&z)[j] = arow[r][k + j];
                pa[r] = z;
            }
        }
        #pragma unroll
        for (int r = 0; r < 2; ++r) {
            if (k + 3 < K) pw[r] = *(const float4*)(wrow[r] + k);
            else {
                float4 z = {0.f,0.f,0.f,0.f};
                #pragma unroll
                for (int j = 0; j < 4; ++j) if (k + j < K) ((float*)&z)[j] = wrow[r][k + j];
                pw[r] = z;
            }
        }
    }

    for (int ki = 0; ki < Kiter; ++ki) {
        #pragma unroll
        for (int r = 0; r < 4; ++r) {
            int mm = sr + 32 * r;
            As[sq * 4 + 0][mm] = pa[r].x;
            As[sq * 4 + 1][mm] = pa[r].y;
            As[sq * 4 + 2][mm] = pa[r].z;
            As[sq * 4 + 3][mm] = pa[r].w;
        }
        #pragma unroll
        for (int r = 0; r < 2; ++r) {
            int nn = sr + 32 * r;
            Ws[sq * 4 + 0][nn] = pw[r].x;
            Ws[sq * 4 + 1][nn] = pw[r].y;
            Ws[sq * 4 + 2][nn] = pw[r].z;
            Ws[sq * 4 + 3][nn] = pw[r].w;
        }
        __syncthreads();

        if (ki + 1 < Kiter) {
            int k = (ki + 1) * 32 + sq * 4;
            #pragma unroll
            for (int r = 0; r < 4; ++r) {
                if (k + 3 < K) pa[r] = *(const float4*)(arow[r] + k);
                else {
                    float4 z = {0.f,0.f,0.f,0.f};
                    #pragma unroll
                    for (int j = 0; j < 4; ++j) if (k + j < K) ((float*)&z)[j] = arow[r][k + j];
                    pa[r] = z;
                }
            }
            #pragma unroll
            for (int r = 0; r < 2; ++r) {
                if (k + 3 < K) pw[r] = *(const float4*)(wrow[r] + k);
                else {
                    float4 z = {0.f,0.f,0.f,0.f};
                    #pragma unroll
                    for (int j = 0; j < 4; ++j) if (k + j < K) ((float*)&z)[j] = wrow[r][k + j];
                    pw[r] = z;
                }
            }
        }

        #pragma unroll
        for (int kk = 0; kk < 32; ++kk) {
            ull a[4];
            a[0] = *(const ull*)&As[kk][ty * 8 + 0];
            a[1] = *(const ull*)&As[kk][ty * 8 + 2];
            a[2] = *(const ull*)&As[kk][ty * 8 + 4];
            a[3] = *(const ull*)&As[kk][ty * 8 + 6];
            float4 wv = *(const float4*)&Ws[kk][tx * 4];
            ull w[4];
            w[0] = pack2(wv.x, wv.x);
            w[1] = pack2(wv.y, wv.y);
            w[2] = pack2(wv.z, wv.z);
            w[3] = pack2(wv.w, wv.w);
            #pragma unroll
            for (int mp = 0; mp < 4; ++mp)
                #pragma unroll
                for (int n = 0; n < 4; ++n)
                    acc[mp][n] = ffma2(a[mp], w[n], acc[mp][n]);
        }
        __syncthreads();
    }

    float bs[4];
    #pragma unroll
    for (int n = 0; n < 4; ++n) bs[n] = bias[n0 + tx * 4 + n];

    #pragma unroll
    for (int mp = 0; mp < 4; ++mp) {
        float2 v[4];
        #pragma unroll
        for (int n = 0; n < 4; ++n) v[n] = unpack2(acc[mp][n]);
        size_t r0 = (size_t)(m0 + ty * 8 + mp * 2 + 0) * N + n0 + tx * 4;
        size_t r1 = (size_t)(m0 + ty * 8 + mp * 2 + 1) * N + n0 + tx * 4;
        float4 o;
        o.x = v[0].x + bs[0]; o.y = v[1].x + bs[1]; o.z = v[2].x + bs[2]; o.w = v[3].x + bs[3];
        *(float4*)&C[r0] = o;
        o.x = v[0].y + bs[0]; o.y = v[1].y + bs[1]; o.z = v[2].y + bs[2]; o.w = v[3].y + bs[3];
        *(float4*)&C[r1] = o;
    }
}

// ---------------- persistent GRU recurrence: 256 CTAs, 2/SM, chain interleave ----------------
// 256 CTAs = 64 ug x 4 bg. CTA owns 8 units (24 W rows) x 16 batches. Two CTAs
// co-resident per SM; different-bg chains fill each other's latency bubbles.
// Compute thread: warp=ks (k-split 8), lane = bq(8: 2 batches) x rg(4: 3 row-pairs).
// Per k: 1 LDS.64 h + 3 LDS.64 w-pairs + 2 dup-packs + 6 FFMA2.

#define RS_WT    0                                  // [k512][24] = 49152 B
#define RS_HT    49152                              // [2 chunks][256k][16b] = 32768 B
#define RS_RED   81920                              // [ks8][pos32][6 ull] = 12288 B
#define RS_XPS   94208                              // [3g][16b][8u] = 1536 B
#define RS_TOTAL 95744

__global__ void __launch_bounds__(256, 2) recur_kernel(
    const float* __restrict__ xp, const float* __restrict__ Whh,
    const float* __restrict__ bhh, float* __restrict__ hg,
    float* __restrict__ hist, float* __restrict__ pooledp)
{
    extern __shared__ char smem_raw[];
    float* wt   = (float*)(smem_raw + RS_WT);
    float* h_ts = (float*)(smem_raw + RS_HT);
    ull*   red  = (ull*)  (smem_raw + RS_RED);
    float* xps  = (float*)(smem_raw + RS_XPS);

    const int tid = threadIdx.x;
    const int ug  = blockIdx.x >> 2;
    const int bg  = blockIdx.x & 3;
    const int u0  = ug * 8;
    const int b0  = bg * 16;
    unsigned int* cnt = &g_arrive4[bg * 32];

    // stage W slice: 24 rows (3 gates x 8 units), wt[k*24 + g*8 + j]
    // (unit pairs (j, j+1) adjacent -> natural f32x2 w-pairs)
    for (int r = 0; r < 24; ++r) {
        int g = r >> 3, j = r & 7;
        const float* row = Whh + (size_t)(g * 512 + u0 + j) * 512;
        for (int k = tid; k < 512; k += 256) wt[k * 24 + g * 8 + j] = row[k];
    }

    // epilogue ids (tid < 128): one output (b, uu)
    const int b  = tid & 15;
    const int uu = tid >> 4;       // 0..7 for tid<128
    const float bh0 = (tid < 128) ? bhh[u0 + uu] : 0.f;
    const float bh1 = (tid < 128) ? bhh[512 + u0 + uu] : 0.f;
    const float bh2 = (tid < 128) ? bhh[1024 + u0 + uu] : 0.f;

    // compute ids
    const int lane = tid & 31;
    const int ks   = tid >> 5;       // k-split warp
    const int bq   = lane & 7;       // batch pair (2 batches)
    const int rg   = lane >> 3;      // row-pair triple (3 pairs = 6 rows)

    const uint32_t hts_base = smem_u32(h_ts);
    __syncthreads();

    unsigned int epoch = 0;
    float hprev = 0.f;

    for (int t = 0; t < T_; ++t) {
        // stage xp[t] slice: [g][b][8u] (96 float4 loads)
        if (tid < 96) {
            int g = tid / 32, rem = tid & 31;
            int bb = rem >> 1, q = rem & 1;
            *(float4*)&xps[g * 128 + bb * 8 + q * 4] =
                *(const float4*)(xp + ((size_t)t * 64 + b0 + bb) * G3H_ + g * 512 + u0 + q * 4);
        }

        ull acc[2][3];                 // [batch m][row-pair pp]
        #pragma unroll
        for (int m = 0; m < 2; ++m)
            #pragma unroll
            for (int pp = 0; pp < 3; ++pp) acc[m][pp] = 0ull;

        if (t > 0) {
            const float* hp = hg + ((size_t)((t - 1) & 1) * 4 + bg) * 8192;
            // issue both 16KB chunks
            #pragma unroll
            for (int c = 0; c < 2; ++c) {
                uint32_t dst = hts_base + c * 16384;
                const float* src = hp + c * 4096;
                #pragma unroll
                for (int q = 0; q < 4; ++q) {
                    int idx = tid + q * 256;
                    cp_async16(dst + idx * 16, src + idx * 4);
                }
                asm volatile("cp.async.commit_group;" ::: "memory");
            }
            #pragma unroll 1
            for (int c = 0; c < 2; ++c) {
                if (c == 0) asm volatile("cp.async.wait_group 1;" ::: "memory");
                else        asm volatile("cp.async.wait_group 0;" ::: "memory");
                __syncthreads();

                const float* hb = h_ts + c * 4096;
                #pragma unroll
                for (int i = 0; i < 32; ++i) {
                    int kk = ks * 32 + i;           // 0..255 within chunk
                    int k  = c * 256 + kk;
                    float2 hv = *(const float2*)&hb[kk * 16 + bq * 2];
                    const float* wr = &wt[k * 24 + rg * 6];
                    ull wp0 = *(const ull*)(wr + 0);
                    ull wp1 = *(const ull*)(wr + 2);
                    ull wp2 = *(const ull*)(wr + 4);
                    ull hd0 = pack2(hv.x, hv.x);
                    ull hd1 = pack2(hv.y, hv.y);
                    acc[0][0] = ffma2(hd0, wp0, acc[0][0]);
                    acc[0][1] = ffma2(hd0, wp1, acc[0][1]);
                    acc[0][2] = ffma2(hd0, wp2, acc[0][2]);
                    acc[1][0] = ffma2(hd1, wp0, acc[1][0]);
                    acc[1][1] = ffma2(hd1, wp1, acc[1][1]);
                    acc[1][2] = ffma2(hd1, wp2, acc[1][2]);
                }
            }
        }

        // ---- cross-ks reduction ----
        __syncthreads();   // also covers xps staging when t==0
        {
            ull* rp = &red[(ks * 32 + rg * 8 + bq) * 6];
            #pragma unroll
            for (int m = 0; m < 2; ++m)
                #pragma unroll
                for (int pp = 0; pp < 3; ++pp) rp[m * 3 + pp] = acc[m][pp];
        }
        __syncthreads();

        // ---- epilogue: thread (b, uu), tid < 128 ----
        float hnew = 0.f;
        if (tid < 128) {
            const float* redf = (const float*)red;
            float gh[3];
            #pragma unroll
            for (int g = 0; g < 3; ++g) {
                int row = g * 8 + uu;
                int p = row >> 1, half = row & 1;
                int rgE = p / 3, ppE = p % 3;
                int base = ((rgE * 8 + (b >> 1)) * 6 + (b & 1) * 3 + ppE) * 2 + half;
                float s = 0.f;
                #pragma unroll
                for (int kw = 0; kw < 8; ++kw) s += redf[base + kw * 384];
                gh[g] = s;
            }

            float xr = xps[0 * 128 + b * 8 + uu];
            float xz = xps[1 * 128 + b * 8 + uu];
            float xn = xps[2 * 128 + b * 8 + uu];

            float r = 1.f / (1.f + __expf(-(xr + gh[0] + bh0)));
            float z = 1.f / (1.f + __expf(-(xz + gh[1] + bh1)));
            float nn = tanhf(xn + r * (gh[2] + bh2));
            hnew = (1.f - z) * nn + z * hprev;
            hprev = hnew;

            hg[((size_t)(t & 1) * 4 + bg) * 8192 + (u0 + uu) * 16 + b] = hnew;
            if (hist) hist[((size_t)t * 64 + b0 + b) * 512 + u0 + uu] = hnew;

            if (pooledp) {
                float s = hnew;
                s += __shfl_down_sync(0xffffffffu, s, 8, 16);
                s += __shfl_down_sync(0xffffffffu, s, 4, 16);
                s += __shfl_down_sync(0xffffffffu, s, 2, 16);
                s += __shfl_down_sync(0xffffffffu, s, 1, 16);
                if (b == 0)
                    pooledp[(size_t)bg * T_ * 512 + t * 512 + u0 + uu] = s;
            }
        }

        if (t < T_ - 1) group_barrier(&epoch, cnt);
    }
}

// ---------------- final FC: combine 4 pooled partials + project ----------------
__global__ void fc_kernel(const float* __restrict__ pooledp, const float* __restrict__ fcW,
                          const float* __restrict__ fcb, float* __restrict__ out)
{
    int t    = blockIdx.x;
    int lane = threadIdx.x;
    float acc[L_];
    #pragma unroll
    for (int l = 0; l < L_; ++l) acc[l] = 0.f;
    for (int k = lane; k < 512; k += 32) {
        float p = pooledp[0 * T_ * 512 + t * 512 + k]
                + pooledp[1 * T_ * 512 + t * 512 + k]
                + pooledp[2 * T_ * 512 + t * 512 + k]
                + pooledp[3 * T_ * 512 + t * 512 + k];
        p *= (1.0f / 64.0f);
        #pragma unroll
        for (int l = 0; l < L_; ++l) acc[l] = fmaf(p, fcW[l * 512 + k], acc[l]);
    }
    #pragma unroll
    for (int l = 0; l < L_; ++l) {
        #pragma unroll
        for (int off = 16; off > 0; off >>= 1)
            acc[l] += __shfl_down_sync(0xffffffffu, acc[l], off);
    }
    if (lane == 0) {
        #pragma unroll
        for (int l = 0; l < L_; ++l) out[t * L_ + l] = acc[l] + fcb[l];
    }
}

// ---------------- launch ----------------
extern "C" void kernel_launch(void* const* d_in, const int* in_sizes, int n_in,
                              void* d_out, int out_size)
{
    const int*   texts = (const int*)  d_in[0];
    const float* emb   = (const float*)d_in[1];
    const float* Wih0  = (const float*)d_in[2];
    const float* Whh0  = (const float*)d_in[3];
    const float* bih0  = (const float*)d_in[4];
    const float* bhh0  = (const float*)d_in[5];
    const float* Wih1  = (const float*)d_in[6];
    const float* Whh1  = (const float*)d_in[7];
    const float* bih1  = (const float*)d_in[8];
    const float* bhh1  = (const float*)d_in[9];
    const float* fcW   = (const float*)d_in[10];
    const float* fcb   = (const float*)d_in[11];
    float* out = (float*)d_out;

    float *xp0, *xp1, *h1, *hT, *pooledp;
    cudaGetSymbolAddress((void**)&xp0,     g_xp0);
    cudaGetSymbolAddress((void**)&xp1,     g_xp1);
    cudaGetSymbolAddress((void**)&h1,      g_h1);
    cudaGetSymbolAddress((void**)&hT,      g_hT);
    cudaGetSymbolAddress((void**)&pooledp, g_pooledp);

    static bool attr_set = false;
    if (!attr_set) {
        cudaFuncSetAttribute(recur_kernel,
                             cudaFuncAttributeMaxDynamicSharedMemorySize, RS_TOTAL);
        attr_set = true;
    }

    const int M = T_ * B_;                  // 32768
    dim3 ggrid(G3H_ / 64, M / 128);         // (24, 256)

    // layer 0 input projection (embedding gather fused)
    gemm_kernel<<<ggrid, 256>>>(emb, texts, Wih0, bih0, xp0, M, G3H_, E_);

    // layer 0 recurrence -> h1 history ([t*B+b][H] for the next GEMM)
    init_kernel<<<1, 128>>>();
    recur_kernel<<<NBLK, NTHR, RS_TOTAL>>>(xp0, Whh0, bhh0, hT, h1, nullptr);

    // layer 1 input projection
    gemm_kernel<<<ggrid, 256>>>(h1, nullptr, Wih1, bih1, xp1, M, G3H_, H_);

    // layer 1 recurrence + partial batch-mean pooling
    init_kernel<<<1, 128>>>();
    recur_kernel<<<NBLK, NTHR, RS_TOTAL>>>(xp1, Whh1, bhh1, hT, nullptr, pooledp);

    // final projection
    fc_kernel<<<T_, 32>>>(pooledp, fcW, fcb, out);
}